// round 1
// baseline (speedup 1.0000x reference)
#include <cuda_runtime.h>
#include <math.h>

#define BATCH   16
#define CHAN    512
#define NPIX    1024
#define HEADS   8
#define DHEAD   64
#define NGROUPS 32

// ---------------- scratch (no allocations allowed) ----------------
__device__ float g_xn [BATCH * CHAN * NPIX];          // 32 MB  group-normed x
__device__ float g_qkv[BATCH * 3 * CHAN * NPIX];      // 96 MB  qkv
__device__ float g_att[BATCH * CHAN * NPIX];          // 32 MB  attention output

// =================================================================
// GroupNorm32: one block per (batch, group). Group = 16 channels x 1024
// pixels = 16384 contiguous floats.
// =================================================================
__global__ __launch_bounds__(256) void groupnorm_kernel(
    const float* __restrict__ x, const float* __restrict__ gamma,
    const float* __restrict__ beta, float* __restrict__ out)
{
    const int GE = (CHAN / NGROUPS) * NPIX;  // 16384
    int bg = blockIdx.x;
    const float* xp = x + (size_t)bg * GE;
    float* op = out + (size_t)bg * GE;
    int tid = threadIdx.x;

    float s = 0.f, ss = 0.f;
    for (int i = tid * 4; i < GE; i += 256 * 4) {
        float4 v = *(const float4*)(xp + i);
        s  += v.x + v.y + v.z + v.w;
        ss += v.x * v.x + v.y * v.y + v.z * v.z + v.w * v.w;
    }
    __shared__ float rs[8], rss[8];
    #pragma unroll
    for (int off = 16; off; off >>= 1) {
        s  += __shfl_xor_sync(0xffffffffu, s, off);
        ss += __shfl_xor_sync(0xffffffffu, ss, off);
    }
    int warp = tid >> 5;
    if ((tid & 31) == 0) { rs[warp] = s; rss[warp] = ss; }
    __syncthreads();
    if (tid == 0) {
        float a = 0.f, b2 = 0.f;
        #pragma unroll
        for (int i = 0; i < 8; i++) { a += rs[i]; b2 += rss[i]; }
        rs[0] = a; rss[0] = b2;
    }
    __syncthreads();
    float mean = rs[0] * (1.0f / GE);
    float var  = rss[0] * (1.0f / GE) - mean * mean;
    float inv  = rsqrtf(var + 1e-6f);

    int g = bg & (NGROUPS - 1);
    for (int i = tid * 4; i < GE; i += 256 * 4) {
        int c = g * 16 + (i >> 10);           // 1024 pixels per channel
        float ga = gamma[c] * inv;
        float be = beta[c];
        float4 v = *(const float4*)(xp + i);
        v.x = (v.x - mean) * ga + be;
        v.y = (v.y - mean) * ga + be;
        v.z = (v.z - mean) * ga + be;
        v.w = (v.w - mean) * ga + be;
        *(float4*)(op + i) = v;
    }
}

// =================================================================
// Batched GEMM: C[b,m,p] = sum_c A[m,c]*B[b,c,p] + bias[m] (+ resid[b,m,p])
// K = 512 fixed, N = 1024. BM=BN=128, BK=8, 256 threads, 8x8 microtile.
// =================================================================
__global__ __launch_bounds__(256) void gemm512_kernel(
    const float* __restrict__ A, const float* __restrict__ B,
    const float* __restrict__ bias, const float* __restrict__ resid,
    float* __restrict__ C, int M)
{
    const int K = CHAN, N = NPIX;
    int bb = blockIdx.z;
    int m0 = blockIdx.y * 128;
    int n0 = blockIdx.x * 128;
    const float* Bb = B + (size_t)bb * K * N;
    float* Cb = C + (size_t)bb * M * N;

    __shared__ float As[8][128];
    __shared__ float Bs[8][128];

    int tid  = threadIdx.x;
    int arow = tid >> 1;             // 0..127
    int acol = (tid & 1) << 2;       // 0 / 4
    int brow = tid >> 5;             // 0..7
    int bcol = (tid & 31) << 2;      // 0..124
    int ty = tid >> 4;               // 0..15
    int tx = tid & 15;               // 0..15

    float acc[8][8];
    #pragma unroll
    for (int i = 0; i < 8; i++)
        #pragma unroll
        for (int j = 0; j < 8; j++) acc[i][j] = 0.f;

    const float* aPtr = A  + (size_t)(m0 + arow) * K + acol;
    const float* bPtr = Bb + (size_t)brow * N + n0 + bcol;

    for (int k0 = 0; k0 < K; k0 += 8) {
        float4 av = *(const float4*)(aPtr + k0);
        float4 bv = *(const float4*)(bPtr + (size_t)k0 * N);
        __syncthreads();
        As[acol + 0][arow] = av.x;
        As[acol + 1][arow] = av.y;
        As[acol + 2][arow] = av.z;
        As[acol + 3][arow] = av.w;
        *(float4*)&Bs[brow][bcol] = bv;
        __syncthreads();
        #pragma unroll
        for (int kk = 0; kk < 8; kk++) {
            float ra[8], rb[8];
            *(float4*)(ra)     = *(const float4*)&As[kk][ty * 8];
            *(float4*)(ra + 4) = *(const float4*)&As[kk][ty * 8 + 4];
            *(float4*)(rb)     = *(const float4*)&Bs[kk][tx * 8];
            *(float4*)(rb + 4) = *(const float4*)&Bs[kk][tx * 8 + 4];
            #pragma unroll
            for (int i = 0; i < 8; i++)
                #pragma unroll
                for (int j = 0; j < 8; j++)
                    acc[i][j] = fmaf(ra[i], rb[j], acc[i][j]);
        }
    }

    #pragma unroll
    for (int i = 0; i < 8; i++) {
        int m = m0 + ty * 8 + i;
        float bi = bias[m];
        float* cp = Cb + (size_t)m * N + n0 + tx * 8;
        const float* rp = resid ? (resid + (size_t)bb * M * N + (size_t)m * N + n0 + tx * 8)
                                : (const float*)0;
        #pragma unroll
        for (int jv = 0; jv < 8; jv += 4) {
            float4 r;
            r.x = acc[i][jv + 0] + bi;
            r.y = acc[i][jv + 1] + bi;
            r.z = acc[i][jv + 2] + bi;
            r.w = acc[i][jv + 3] + bi;
            if (rp) {
                float4 xv = *(const float4*)(rp + jv);
                r.x += xv.x; r.y += xv.y; r.z += xv.z; r.w += xv.w;
            }
            *(float4*)(cp + jv) = r;
        }
    }
}

// =================================================================
// Flash-style attention. qkv layout: [b][3*512][1024] with q:[0,512),
// k:[512,1024), v:[1024,1536); within each, channel = head*64 + dd.
// Block = (query tile of 64, head, batch); 256 threads; online softmax.
// out[b][h*64+dd][q] = sum_m softmax_m(scale * q.k)[q,m] * v[dd,m]
// =================================================================
#define SROW 65   // smem row pitch (64 + 1 pad)

__global__ __launch_bounds__(256) void attn_kernel(
    const float* __restrict__ qkv, float* __restrict__ out)
{
    const int n = NPIX;
    extern __shared__ float sm[];
    float* Qs = sm;
    float* Ks = sm + 64 * SROW;
    float* Vs = sm + 2 * 64 * SROW;
    float* Ps = sm + 3 * 64 * SROW;

    int qt = blockIdx.x * 64;
    int hh = blockIdx.y, bb = blockIdx.z;
    const float* Qg = qkv + ((size_t)bb * 1536 + hh * 64) * n + qt;
    const float* Kg = qkv + ((size_t)bb * 1536 + 512 + hh * 64) * n;
    const float* Vg = qkv + ((size_t)bb * 1536 + 1024 + hh * 64) * n;
    float* Og = out + ((size_t)bb * CHAN + hh * 64) * n + qt;

    int tid = threadIdx.x;
    int ty = tid >> 4;     // 0..15 -> query quads
    int tx = tid & 15;     // 0..15 -> key/d quads

    for (int idx = tid; idx < 64 * 64; idx += 256) {
        int dd = idx >> 6, q = idx & 63;
        Qs[dd * SROW + q] = Qg[(size_t)dd * n + q];
    }

    float m_i[4], l_i[4], oa[4][4];
    #pragma unroll
    for (int i = 0; i < 4; i++) {
        m_i[i] = -1e30f; l_i[i] = 0.f;
        #pragma unroll
        for (int j = 0; j < 4; j++) oa[i][j] = 0.f;
    }
    const float scale = 0.125f;   // d^-0.5, d=64

    for (int kt = 0; kt < n; kt += 64) {
        __syncthreads();   // prev iter done with Ks/Vs/Ps
        for (int idx = tid; idx < 64 * 64; idx += 256) {
            int dd = idx >> 6, k = idx & 63;
            Ks[dd * SROW + k] = Kg[(size_t)dd * n + kt + k];
            Vs[dd * SROW + k] = Vg[(size_t)dd * n + kt + k];
        }
        __syncthreads();

        // S = (Q tile)^T (K tile)
        float s[4][4];
        #pragma unroll
        for (int i = 0; i < 4; i++)
            #pragma unroll
            for (int j = 0; j < 4; j++) s[i][j] = 0.f;

        #pragma unroll 8
        for (int dd = 0; dd < 64; dd++) {
            float qv[4], kv[4];
            #pragma unroll
            for (int i = 0; i < 4; i++) qv[i] = Qs[dd * SROW + ty * 4 + i];
            #pragma unroll
            for (int j = 0; j < 4; j++) kv[j] = Ks[dd * SROW + tx * 4 + j];
            #pragma unroll
            for (int i = 0; i < 4; i++)
                #pragma unroll
                for (int j = 0; j < 4; j++)
                    s[i][j] = fmaf(qv[i], kv[j], s[i][j]);
        }

        // online softmax per query row (16 lanes of same ty hold the row)
        #pragma unroll
        for (int i = 0; i < 4; i++) {
            #pragma unroll
            for (int j = 0; j < 4; j++) s[i][j] *= scale;
            float mx = fmaxf(fmaxf(s[i][0], s[i][1]), fmaxf(s[i][2], s[i][3]));
            #pragma unroll
            for (int off = 8; off; off >>= 1)
                mx = fmaxf(mx, __shfl_xor_sync(0xffffffffu, mx, off, 16));
            float mnew = fmaxf(m_i[i], mx);
            float alpha = __expf(m_i[i] - mnew);
            float rsum = 0.f;
            #pragma unroll
            for (int j = 0; j < 4; j++) {
                float p = __expf(s[i][j] - mnew);
                s[i][j] = p;
                rsum += p;
            }
            #pragma unroll
            for (int off = 8; off; off >>= 1)
                rsum += __shfl_xor_sync(0xffffffffu, rsum, off, 16);
            l_i[i] = l_i[i] * alpha + rsum;
            m_i[i] = mnew;
            #pragma unroll
            for (int j = 0; j < 4; j++) oa[i][j] *= alpha;
        }

        // P to smem, then O += P @ V^T
        #pragma unroll
        for (int i = 0; i < 4; i++)
            #pragma unroll
            for (int j = 0; j < 4; j++)
                Ps[(ty * 4 + i) * SROW + tx * 4 + j] = s[i][j];
        __syncthreads();

        #pragma unroll 8
        for (int kk = 0; kk < 64; kk++) {
            float pv[4], vv[4];
            #pragma unroll
            for (int i = 0; i < 4; i++) pv[i] = Ps[(ty * 4 + i) * SROW + kk];
            #pragma unroll
            for (int j = 0; j < 4; j++) vv[j] = Vs[(tx * 4 + j) * SROW + kk];
            #pragma unroll
            for (int i = 0; i < 4; i++)
                #pragma unroll
                for (int j = 0; j < 4; j++)
                    oa[i][j] = fmaf(pv[i], vv[j], oa[i][j]);
        }
    }

    // normalize, stage transposed [d][q] for coalesced store
    __syncthreads();
    #pragma unroll
    for (int i = 0; i < 4; i++) {
        float invl = 1.0f / l_i[i];
        #pragma unroll
        for (int j = 0; j < 4; j++)
            Ps[(tx * 4 + j) * SROW + ty * 4 + i] = oa[i][j] * invl;
    }
    __syncthreads();
    for (int idx = tid; idx < 64 * 64; idx += 256) {
        int dd = idx >> 6, q = idx & 63;
        Og[(size_t)dd * n + q] = Ps[dd * SROW + q];
    }
}

// =================================================================
extern "C" void kernel_launch(void* const* d_in, const int* in_sizes, int n_in,
                              void* d_out, int out_size)
{
    const float* x      = (const float*)d_in[0];
    const float* w_qkv  = (const float*)d_in[1];
    const float* b_qkv  = (const float*)d_in[2];
    const float* w_proj = (const float*)d_in[3];
    const float* b_proj = (const float*)d_in[4];
    const float* gamma  = (const float*)d_in[5];
    const float* beta   = (const float*)d_in[6];
    float* out = (float*)d_out;

    float *xn, *qkvp, *attp;
    cudaGetSymbolAddress((void**)&xn,   g_xn);
    cudaGetSymbolAddress((void**)&qkvp, g_qkv);
    cudaGetSymbolAddress((void**)&attp, g_att);

    const int attn_smem = 4 * 64 * SROW * (int)sizeof(float);  // 66560 B
    cudaFuncSetAttribute(attn_kernel, cudaFuncAttributeMaxDynamicSharedMemorySize, attn_smem);

    // 1. GroupNorm
    groupnorm_kernel<<<BATCH * NGROUPS, 256>>>(x, gamma, beta, xn);
    // 2. QKV 1x1 conv: [1536,512] x [512,1024] per batch
    gemm512_kernel<<<dim3(NPIX / 128, 1536 / 128, BATCH), 256>>>(
        w_qkv, xn, b_qkv, (const float*)0, qkvp, 1536);
    // 3. Attention
    attn_kernel<<<dim3(NPIX / 64, HEADS, BATCH), 256, attn_smem>>>(qkvp, attp);
    // 4. Proj + bias + residual
    gemm512_kernel<<<dim3(NPIX / 128, CHAN / 128, BATCH), 256>>>(
        w_proj, attp, b_proj, x, out, CHAN);
}